// round 13
// baseline (speedup 1.0000x reference)
#include <cuda_runtime.h>
#include <cuda_fp16.h>
#include <cstdint>
#include <math.h>

#define CDIM 128
#define BT   128
#define LDH  136            // fp16 tile row stride (272B: conflict-free, 16B aligned)
#define LDW  136            // fp16 weight row stride
#define NTHREADS 512
#define EPSF 1e-8f
#define WCOMP_BYTES (CDIM * LDW * 2)   // 34816 bytes per weight image
#define WCHUNKS (WCOMP_BYTES / 16)     // 2176

// Weight images, fp16, B[n][k] = W[k][n] (padded rows).
// slots: 0=Wgcn 1=gM0(Wq_m@Wk_m^T/sqrtC) 2=gM1 3=Wv_m 4=Wv_d 5=W1
__device__ __align__(16) __half g_Wpad[6][CDIM * LDW];

// ---------------- helpers ----------------
__device__ __forceinline__ uint32_t smem_u32(const void* p) {
    uint32_t a;
    asm("{ .reg .u64 t; cvta.to.shared.u64 t, %1; cvt.u32.u64 %0, t; }" : "=r"(a) : "l"(p));
    return a;
}
__device__ __forceinline__ uint32_t cvt2h(float a, float b) {
    __half2 h = __floats2half2_rn(a, b);
    return *reinterpret_cast<uint32_t*>(&h);
}
__device__ __forceinline__ float2 up2(const __half* p) {
    return __half22float2(*reinterpret_cast<const __half2*>(p));
}
__device__ __forceinline__ void mma_f16(float c[4], const uint32_t a[4], uint32_t b0, uint32_t b1) {
    asm volatile("mma.sync.aligned.m16n8k16.row.col.f32.f16.f16.f32 "
        "{%0,%1,%2,%3}, {%4,%5,%6,%7}, {%8,%9}, {%0,%1,%2,%3};"
        : "+f"(c[0]), "+f"(c[1]), "+f"(c[2]), "+f"(c[3])
        : "r"(a[0]), "r"(a[1]), "r"(a[2]), "r"(a[3]), "r"(b0), "r"(b1));
}
#define LDSM4(r0_, r1_, r2_, r3_, addr) asm volatile( \
    "ldmatrix.sync.aligned.m8n8.x4.shared.b16 {%0,%1,%2,%3}, [%4];" \
    : "=r"(r0_), "=r"(r1_), "=r"(r2_), "=r"(r3_) : "r"(addr))

#define CPA16(s, g)   asm volatile("cp.async.cg.shared.global [%0], [%1], 16;" :: "r"(s), "l"(g))
#define CPA_COMMIT()  asm volatile("cp.async.commit_group;" ::: "memory")
#define CPA_WAIT(n)   asm volatile("cp.async.wait_group %0;" :: "n"(n) : "memory")

#define QR(v) do { v += __shfl_xor_sync(0xffffffffu, v, 1); \
                   v += __shfl_xor_sync(0xffffffffu, v, 2); } while (0)

__device__ __forceinline__ void cpa_load(const __half* g, uint32_t s_base) {
    const char* gp = reinterpret_cast<const char*>(g);
    for (int i = threadIdx.x; i < WCHUNKS; i += NTHREADS)
        CPA16(s_base + (uint32_t)(i * 16), gp + (size_t)i * 16);
    CPA_COMMIT();
}

// ---------------- merged prep kernel ----------------
__global__ void prep_all(const float* __restrict__ Wgcn, const float* __restrict__ Wvm,
                         const float* __restrict__ Wvd,  const float* __restrict__ W1,
                         const float* __restrict__ Wq_m, const float* __restrict__ Wk_m,
                         const float* __restrict__ Wq_d, const float* __restrict__ Wk_d) {
    int b = blockIdx.x;
    if (b < 64) {
        int slot4 = b >> 4;
        const float* W; int slot;
        switch (slot4) {
            case 0:  W = Wgcn; slot = 0; break;
            case 1:  W = Wvm;  slot = 3; break;
            case 2:  W = Wvd;  slot = 4; break;
            default: W = W1;   slot = 5; break;
        }
        int e0 = (b & 15) * 1024;
        for (int e = e0 + threadIdx.x; e < e0 + 1024; e += blockDim.x) {
            int n = e >> 7, k = e & 127;
            g_Wpad[slot][n * LDW + k] = __float2half_rn(W[k * CDIM + n]);
        }
    } else {
        __shared__ float krow[CDIM];
        int bb = b - 64;
        int which = bb >> 7;
        int n = bb & 127;
        const float* Wq = which ? Wq_d : Wq_m;
        const float* Wk = which ? Wk_d : Wk_m;
        if (threadIdx.x < CDIM) krow[threadIdx.x] = Wk[n * CDIM + threadIdx.x];
        __syncthreads();
        if (threadIdx.x < CDIM) {
            int k = threadIdx.x;
            const float4* q4 = reinterpret_cast<const float4*>(Wq + k * CDIM);
            float s = 0.f;
#pragma unroll
            for (int c4 = 0; c4 < CDIM / 4; ++c4) {
                float4 q = q4[c4];
                s = fmaf(q.x, krow[c4 * 4 + 0], s);
                s = fmaf(q.y, krow[c4 * 4 + 1], s);
                s = fmaf(q.z, krow[c4 * 4 + 2], s);
                s = fmaf(q.w, krow[c4 * 4 + 3], s);
            }
            g_Wpad[which ? 2 : 1][n * LDW + k] = __float2half_rn(s * 0.0883883476483184f);
        }
    }
}

// ---------------- SMEM layout (all tiles fp16, BT=128, dual weight buf) ----------------
#define H_MS   0
#define H_DS   (BT * LDH)
#define H_X1M  (2 * BT * LDH)
#define H_X1D  (3 * BT * LDH)
#define WB0_BYTES (4 * BT * LDH * 2)                 // 139264
#define WB1_BYTES (WB0_BYTES + WCOMP_BYTES)          // 174080
#define F_R0   ((WB1_BYTES + WCOMP_BYTES) / 4)       // 52224 floats
#define F_R1   (F_R0 + 256)
#define F_SAM  (F_R1 + 256)
#define F_SBM  (F_SAM + 128)
#define F_SAD  (F_SBM + 128)
#define F_SBD  (F_SAD + 128)
#define F_SW2  (F_SBD + 128)
#define SMEM_BYTES ((F_SW2 + 128 + 32) * 4)          // ~213.6 KB -> 1 CTA/SM

// ---------------- GEMM (warp tile m16 x n64) ----------------
__device__ __forceinline__ void gemm_a(uint32_t aX, uint32_t wb, float acc[8][4]) {
#pragma unroll
    for (int ks = 0; ks < 8; ++ks) {
        uint32_t a[4];
        LDSM4(a[0], a[1], a[2], a[3], aX + ks * 32);
#pragma unroll
        for (int np = 0; np < 4; ++np) {
            uint32_t off = (uint32_t)(np * (16 * 2 * LDW) + ks * 32);
            uint32_t b0_, b1_, b2_, b3_;
            LDSM4(b0_, b1_, b2_, b3_, wb + off);
            mma_f16(acc[np * 2],     a, b0_, b1_);
            mma_f16(acc[np * 2 + 1], a, b2_, b3_);
        }
    }
}

__device__ __forceinline__ void gemm_comb(const __half* __restrict__ Xa, const __half* __restrict__ Xb,
                                          float ca0, float cb0, float ca1, float cb1,
                                          uint32_t wb, int r0, int cK, float acc[8][4]) {
    const __half* pa0 = Xa + r0 * LDH;
    const __half* pa1 = Xa + (r0 + 8) * LDH;
    const __half* pb0 = Xb + r0 * LDH;
    const __half* pb1 = Xb + (r0 + 8) * LDH;
#pragma unroll
    for (int ks = 0; ks < 8; ++ks) {
        int c0 = ks * 16 + cK;
        uint32_t a[4];
        {
            float2 v0 = up2(pa0 + c0), u0 = up2(pb0 + c0);
            float2 v1 = up2(pa1 + c0), u1 = up2(pb1 + c0);
            float2 v2 = up2(pa0 + c0 + 8), u2 = up2(pb0 + c0 + 8);
            float2 v3 = up2(pa1 + c0 + 8), u3 = up2(pb1 + c0 + 8);
            a[0] = cvt2h(ca0 * v0.x + cb0 * u0.x, ca0 * v0.y + cb0 * u0.y);
            a[1] = cvt2h(ca1 * v1.x + cb1 * u1.x, ca1 * v1.y + cb1 * u1.y);
            a[2] = cvt2h(ca0 * v2.x + cb0 * u2.x, ca0 * v2.y + cb0 * u2.y);
            a[3] = cvt2h(ca1 * v3.x + cb1 * u3.x, ca1 * v3.y + cb1 * u3.y);
        }
#pragma unroll
        for (int np = 0; np < 4; ++np) {
            uint32_t off = (uint32_t)(np * (16 * 2 * LDW) + ks * 32);
            uint32_t b0_, b1_, b2_, b3_;
            LDSM4(b0_, b1_, b2_, b3_, wb + off);
            mma_f16(acc[np * 2],     a, b0_, b1_);
            mma_f16(acc[np * 2 + 1], a, b2_, b3_);
        }
    }
}

__device__ __forceinline__ void gemm_dual(const __half* __restrict__ Ms, const __half* __restrict__ Ds,
                                          float a0, float b0c, float a1, float b1c,
                                          uint32_t wb, int r0, int cK,
                                          float acc0[8][4], float acc1[8][4]) {
    const __half* pm0 = Ms + r0 * LDH;
    const __half* pm1 = Ms + (r0 + 8) * LDH;
    const __half* pd0 = Ds + r0 * LDH;
    const __half* pd1 = Ds + (r0 + 8) * LDH;
#pragma unroll
    for (int ks = 0; ks < 8; ++ks) {
        int c0 = ks * 16 + cK;
        uint32_t x0[4], x1[4];
        {
            float2 m0 = up2(pm0 + c0), d0 = up2(pd0 + c0);
            float2 m1 = up2(pm1 + c0), d1 = up2(pd1 + c0);
            float2 m2 = up2(pm0 + c0 + 8), d2 = up2(pd0 + c0 + 8);
            float2 m3 = up2(pm1 + c0 + 8), d3 = up2(pd1 + c0 + 8);
            x0[0] = cvt2h(a0 * m0.x + b0c * d0.x, a0 * m0.y + b0c * d0.y);
            x0[1] = cvt2h(a1 * m1.x + b1c * d1.x, a1 * m1.y + b1c * d1.y);
            x0[2] = cvt2h(a0 * m2.x + b0c * d2.x, a0 * m2.y + b0c * d2.y);
            x0[3] = cvt2h(a1 * m3.x + b1c * d3.x, a1 * m3.y + b1c * d3.y);
            x1[0] = cvt2h(b0c * m0.x + a0 * d0.x, b0c * m0.y + a0 * d0.y);
            x1[1] = cvt2h(b1c * m1.x + a1 * d1.x, b1c * m1.y + a1 * d1.y);
            x1[2] = cvt2h(b0c * m2.x + a0 * d2.x, b0c * m2.y + a0 * d2.y);
            x1[3] = cvt2h(b1c * m3.x + a1 * d3.x, b1c * m3.y + a1 * d3.y);
        }
#pragma unroll
        for (int np = 0; np < 4; ++np) {
            uint32_t off = (uint32_t)(np * (16 * 2 * LDW) + ks * 32);
            uint32_t b0_, b1_, b2_, b3_;
            LDSM4(b0_, b1_, b2_, b3_, wb + off);
            mma_f16(acc0[np * 2],     x0, b0_, b1_);
            mma_f16(acc0[np * 2 + 1], x0, b2_, b3_);
            mma_f16(acc1[np * 2],     x1, b0_, b1_);
            mma_f16(acc1[np * 2 + 1], x1, b2_, b3_);
        }
    }
}

__global__ __launch_bounds__(NTHREADS, 1)
void mdi_mma_kernel(const float* __restrict__ em, const float* __restrict__ ed,
                    const float* __restrict__ W2, float* __restrict__ out) {
    extern __shared__ float sh[];
    __half* Ms  = reinterpret_cast<__half*>(sh) + H_MS;
    __half* Ds  = reinterpret_cast<__half*>(sh) + H_DS;
    __half* X1m = reinterpret_cast<__half*>(sh) + H_X1M;
    __half* X1d = reinterpret_cast<__half*>(sh) + H_X1D;
    uint32_t wb0_u = smem_u32(reinterpret_cast<char*>(sh) + WB0_BYTES);
    uint32_t wb1_u = smem_u32(reinterpret_cast<char*>(sh) + WB1_BYTES);
    float* R0  = sh + F_R0;
    float* R1  = sh + F_R1;
    float* SAm = sh + F_SAM;
    float* SBm = sh + F_SBM;
    float* SAd = sh + F_SAD;
    float* SBd = sh + F_SBD;
    float* SW2 = sh + F_SW2;

    const int tid  = threadIdx.x;
    const int w    = tid >> 5;
    const int lane = tid & 31;
    const int mb    = (w & 7) * 16;       // warp m-tile base row (8 m-tiles)
    const int nbase = (w >> 3) * 64;      // warp n-half base col
    const int r0    = mb + (lane >> 2);
    const int lq    = lane & 3;
    const int cK    = 2 * lq;
    const int nh    = w >> 3;             // n-half index for reductions
    const int b0 = blockIdx.x * BT;

    // A ldmatrix lane address offset: rows mb+(lane&15), k-half (lane>>4)
    const uint32_t aoff = (uint32_t)((mb + (lane & 15)) * (2 * LDH) + (lane >> 4) * 16);
    const int n_lane = (lane & 7) + ((lane & 16) ? 8 : 0);
    const uint32_t wloff = (uint32_t)((nbase + n_lane) * (2 * LDW) + ((lane >> 3) & 1) * 16);
    const uint32_t wb0l = wb0_u + wloff;
    const uint32_t wb1l = wb1_u + wloff;

    const uint32_t aX1m = smem_u32(X1m) + aoff;
    const uint32_t aX1d = smem_u32(X1d) + aoff;

    // preload: Wgcn -> B0 (G0), gM0 -> B1 (G1)
    cpa_load(g_Wpad[0], wb0_u);
    cpa_load(g_Wpad[1], wb1_u);

    // ---- load inputs -> fp16 tiles, + W2 ----
    {
        const float4* gm = reinterpret_cast<const float4*>(em + (size_t)b0 * CDIM);
        const float4* gd = reinterpret_cast<const float4*>(ed + (size_t)b0 * CDIM);
        for (int i = tid; i < BT * 32; i += NTHREADS) {
            int row = i >> 5, c = i & 31;
            float4 vm = gm[i], vd = gd[i];
            uint2 pm = make_uint2(cvt2h(vm.x, vm.y), cvt2h(vm.z, vm.w));
            uint2 pd = make_uint2(cvt2h(vd.x, vd.y), cvt2h(vd.z, vd.w));
            *reinterpret_cast<uint2*>(Ms + row * LDH + c * 4) = pm;
            *reinterpret_cast<uint2*>(Ds + row * LDH + c * 4) = pd;
        }
        if (tid < CDIM) SW2[tid] = W2[tid];
    }
    __syncthreads();

    // ---- per-batch scalars (quad shfl-reduce; 4 threads/row, 128 rows) ----
    {
        int rr = tid >> 2, part = tid & 3;
        const __half2* mr = reinterpret_cast<const __half2*>(Ms + rr * LDH + part * 32);
        const __half2* dr = reinterpret_cast<const __half2*>(Ds + rr * LDH + part * 32);
        float dman = 0.f, sm2 = 0.f, sd2 = 0.f, md = 0.f;
#pragma unroll
        for (int k = 0; k < 16; ++k) {
            float2 mv = __half22float2(mr[k]);
            float2 dv = __half22float2(dr[k]);
            dman += fabsf(mv.x - dv.x) + fabsf(mv.y - dv.y);
            sm2 += mv.x * mv.x + mv.y * mv.y;
            sd2 += dv.x * dv.x + dv.y * dv.y;
            md  += mv.x * dv.x + mv.y * dv.y;
        }
        QR(dman); QR(sm2); QR(sd2); QR(md);
        if (part == 0) {
            float s3 = 1.f / (1.f + dman);
            float c = md / (sqrtf(sm2 + EPSF) * sqrtf(sd2 + EPSF));
            if (c < 0.f) c *= 0.01f;
            float s1 = 1.f / (1.f + c);
            SAm[rr] = fminf(s3, s1);
            SBm[rr] = fminf(dman * s3, c * s1);
        }
    }

    // ===== pass 0 (merged GCN, B0=Wgcn): x1m/x1d = relu(u @ Wgcn) + x0 =====
    CPA_WAIT(1);          // G0 done (G1 may be in flight)
    __syncthreads();      // Wgcn ready + scalars visible
    {
        float acc0[8][4] = {}, acc1[8][4] = {};
        gemm_dual(Ms, Ds, SAm[r0], SBm[r0], SAm[r0 + 8], SBm[r0 + 8],
                  wb0l, r0, cK, acc0, acc1);
        __syncthreads();                 // all warps done with B0
        cpa_load(g_Wpad[2], wb0_u);      // G2: gM1 -> B0
#pragma unroll
        for (int nt = 0; nt < 8; ++nt) {
            int col = nbase + nt * 8 + cK;
            float2 m0 = up2(&Ms[r0 * LDH + col]);
            float2 m1 = up2(&Ms[(r0 + 8) * LDH + col]);
            float2 d0 = up2(&Ds[r0 * LDH + col]);
            float2 d1 = up2(&Ds[(r0 + 8) * LDH + col]);
            *reinterpret_cast<uint32_t*>(&X1m[r0 * LDH + col]) =
                cvt2h(fmaxf(acc0[nt][0], 0.f) + m0.x, fmaxf(acc0[nt][1], 0.f) + m0.y);
            *reinterpret_cast<uint32_t*>(&X1m[(r0 + 8) * LDH + col]) =
                cvt2h(fmaxf(acc0[nt][2], 0.f) + m1.x, fmaxf(acc0[nt][3], 0.f) + m1.y);
            *reinterpret_cast<uint32_t*>(&X1d[r0 * LDH + col]) =
                cvt2h(fmaxf(acc1[nt][0], 0.f) + d0.x, fmaxf(acc1[nt][1], 0.f) + d0.y);
            *reinterpret_cast<uint32_t*>(&X1d[(r0 + 8) * LDH + col]) =
                cvt2h(fmaxf(acc1[nt][2], 0.f) + d1.x, fmaxf(acc1[nt][3], 0.f) + d1.y);
        }
    }

    // ===== passes 1/2: attention scores per branch (br0: B1=gM0, br1: B0=gM1) =====
#pragma unroll 1
    for (int br = 0; br < 2; ++br) {
        const __half* X1 = br ? X1d : X1m;
        const __half* X0 = br ? Ds : Ms;
        uint32_t aX1 = br ? aX1d : aX1m;
        uint32_t wbl = br ? wb0l : wb1l;
        float acc[8][4] = {};
        CPA_WAIT(1); __syncthreads();    // current gM ready (+ X1 writes visible)
        gemm_a(aX1, wbl, acc);
        __syncthreads();                 // done reading this buffer
        cpa_load(g_Wpad[br ? 4 : 3], br ? wb0_u : wb1_u);   // Wv_m -> B1 / Wv_d -> B0
        {
            float q00 = 0.f, q10 = 0.f, q01 = 0.f, q11 = 0.f;
#pragma unroll
            for (int nt = 0; nt < 8; ++nt) {
                int col = nbase + nt * 8 + cK;
                float2 a0 = up2(&X0[r0 * LDH + col]);
                float2 a1 = up2(&X1[r0 * LDH + col]);
                float2 c0 = up2(&X0[(r0 + 8) * LDH + col]);
                float2 c1 = up2(&X1[(r0 + 8) * LDH + col]);
                q00 += acc[nt][0] * a0.x + acc[nt][1] * a0.y;
                q10 += acc[nt][0] * a1.x + acc[nt][1] * a1.y;
                q01 += acc[nt][2] * c0.x + acc[nt][3] * c0.y;
                q11 += acc[nt][2] * c1.x + acc[nt][3] * c1.y;
            }
            QR(q00); QR(q10); QR(q01); QR(q11);
            if (lq == 0) {
                R0[r0 * 2 + nh] = q00;
                R1[r0 * 2 + nh] = q10;
                R0[(r0 + 8) * 2 + nh] = q01;
                R1[(r0 + 8) * 2 + nh] = q11;
            }
        }
        __syncthreads();
        if (tid < BT) {
            float s0  = R0[tid * 2] + R0[tid * 2 + 1];
            float s1v = R1[tid * 2] + R1[tid * 2 + 1];
            float mx = fmaxf(s0, s1v);
            float e0 = __expf(s0 - mx), e1 = __expf(s1v - mx);
            float inv = 1.f / (e0 + e1);
            if (br == 0) { SAm[tid] = e0 * inv; SBm[tid] = e1 * inv; }
            else         { SAd[tid] = e0 * inv; SBd[tid] = e1 * inv; }
        }
    }

    // ===== pass 3 (B1=Wv_m): mLA = (a0m*x0m + a1m*x1m) @ Wv_m, in registers =====
    float mla[8][4] = {};
    CPA_WAIT(1); __syncthreads();        // Wv_m ready + SAm/SBm visible
    gemm_comb(Ms, X1m, SAm[r0], SBm[r0], SAm[r0 + 8], SBm[r0 + 8], wb1l, r0, cK, mla);
    __syncthreads();                     // done reading B1
    cpa_load(g_Wpad[5], wb1_u);          // G5: W1 -> B1

    // ===== pass 4 (B0=Wv_d): ne = ((a0d*x0d + a1d*x1d) @ Wv_d) * mLA -> X1m =====
    {
        float acc[8][4] = {};
        CPA_WAIT(1); __syncthreads();    // Wv_d ready + SAd/SBd visible
        gemm_comb(Ds, X1d, SAd[r0], SBd[r0], SAd[r0 + 8], SBd[r0 + 8], wb0l, r0, cK, acc);
#pragma unroll
        for (int nt = 0; nt < 8; ++nt) {
            int col = nbase + nt * 8 + cK;
            *reinterpret_cast<uint32_t*>(&X1m[r0 * LDH + col]) =
                cvt2h(acc[nt][0] * mla[nt][0], acc[nt][1] * mla[nt][1]);
            *reinterpret_cast<uint32_t*>(&X1m[(r0 + 8) * LDH + col]) =
                cvt2h(acc[nt][2] * mla[nt][2], acc[nt][3] * mla[nt][3]);
        }
    }

    // ===== pass 5 (B1=W1): pre = relu(ne @ W1) . W2 ; out = sigmoid =====
    {
        float acc[8][4] = {};
        CPA_WAIT(0); __syncthreads();    // W1 ready + ne writes visible
        gemm_a(aX1m, wb1l, acc);
        float p0 = 0.f, p1 = 0.f;
#pragma unroll
        for (int nt = 0; nt < 8; ++nt) {
            int col = nbase + nt * 8 + cK;
            p0 += fmaxf(acc[nt][0], 0.f) * SW2[col] + fmaxf(acc[nt][1], 0.f) * SW2[col + 1];
            p1 += fmaxf(acc[nt][2], 0.f) * SW2[col] + fmaxf(acc[nt][3], 0.f) * SW2[col + 1];
        }
        QR(p0); QR(p1);
        if (lq == 0) {
            R0[r0 * 2 + nh] = p0;
            R0[(r0 + 8) * 2 + nh] = p1;
        }
    }
    __syncthreads();
    if (tid < BT) {
        float pre = R0[tid * 2] + R0[tid * 2 + 1];
        out[b0 + tid] = 1.f / (1.f + __expf(-pre));
    }
}

extern "C" void kernel_launch(void* const* d_in, const int* in_sizes, int n_in,
                              void* d_out, int out_size) {
    const float* em    = (const float*)d_in[0];
    const float* ed    = (const float*)d_in[1];
    const float* Wgcn  = (const float*)d_in[2];
    const float* Wq_m  = (const float*)d_in[3];
    const float* Wk_m  = (const float*)d_in[4];
    const float* Wv_m  = (const float*)d_in[5];
    const float* Wq_d  = (const float*)d_in[6];
    const float* Wk_d  = (const float*)d_in[7];
    const float* Wv_d  = (const float*)d_in[8];
    const float* W1    = (const float*)d_in[9];
    const float* W2    = (const float*)d_in[10];
    float* out = (float*)d_out;

    cudaFuncSetAttribute(mdi_mma_kernel, cudaFuncAttributeMaxDynamicSharedMemorySize, SMEM_BYTES);

    int B = out_size;   // 262144
    prep_all<<<320, 256>>>(Wgcn, Wv_m, Wv_d, W1, Wq_m, Wk_m, Wq_d, Wk_d);
    mdi_mma_kernel<<<B / BT, NTHREADS, SMEM_BYTES>>>(em, ed, W2, out);
}

// round 14
// speedup vs baseline: 1.2674x; 1.2674x over previous
#include <cuda_runtime.h>
#include <cuda_fp16.h>
#include <cstdint>
#include <math.h>

#define CDIM 128
#define BT   64
#define LDH  136            // fp16 tile row stride (272B: conflict-free, 16B aligned)
#define LDW  136            // fp16 weight row stride
#define NTHREADS 256
#define EPSF 1e-8f
#define WCOMP_BYTES (CDIM * LDW * 2)   // 34816 bytes per weight image
#define HALF_BYTES  (WCOMP_BYTES / 2)  // 17408 per n-half
#define HALF_ELEMS  (HALF_BYTES / 2)   // 8704 halves
#define HALF_CHUNKS (HALF_BYTES / 16)  // 1088

// Weight images, fp16, B[n][k] = W[k][n] (padded rows).
// slots: 0=Wgcn 1=gM0(Wq_m@Wk_m^T/sqrtC) 2=gM1 3=Wv_m 4=Wv_d 5=W1
__device__ __align__(16) __half g_Wpad[6][CDIM * LDW];

// ---------------- helpers ----------------
__device__ __forceinline__ uint32_t smem_u32(const void* p) {
    uint32_t a;
    asm("{ .reg .u64 t; cvta.to.shared.u64 t, %1; cvt.u32.u64 %0, t; }" : "=r"(a) : "l"(p));
    return a;
}
__device__ __forceinline__ uint32_t cvt2h(float a, float b) {
    __half2 h = __floats2half2_rn(a, b);
    return *reinterpret_cast<uint32_t*>(&h);
}
__device__ __forceinline__ float2 up2(const __half* p) {
    return __half22float2(*reinterpret_cast<const __half2*>(p));
}
__device__ __forceinline__ void mma_f16(float c[4], const uint32_t a[4], uint32_t b0, uint32_t b1) {
    asm volatile("mma.sync.aligned.m16n8k16.row.col.f32.f16.f16.f32 "
        "{%0,%1,%2,%3}, {%4,%5,%6,%7}, {%8,%9}, {%0,%1,%2,%3};"
        : "+f"(c[0]), "+f"(c[1]), "+f"(c[2]), "+f"(c[3])
        : "r"(a[0]), "r"(a[1]), "r"(a[2]), "r"(a[3]), "r"(b0), "r"(b1));
}
#define LDSM4(r0_, r1_, r2_, r3_, addr) asm volatile( \
    "ldmatrix.sync.aligned.m8n8.x4.shared.b16 {%0,%1,%2,%3}, [%4];" \
    : "=r"(r0_), "=r"(r1_), "=r"(r2_), "=r"(r3_) : "r"(addr))

#define CPA16(s, g)   asm volatile("cp.async.cg.shared.global [%0], [%1], 16;" :: "r"(s), "l"(g))
#define CPA_COMMIT()  asm volatile("cp.async.commit_group;" ::: "memory")
#define CPA_WAIT(n)   asm volatile("cp.async.wait_group %0;" :: "n"(n) : "memory")

// group-local barrier: 128 threads (group grp uses barrier id grp+1)
#define GBAR(grp) asm volatile("bar.sync %0, 128;" :: "r"((grp) + 1) : "memory")

#define QR(v) do { v += __shfl_xor_sync(0xffffffffu, v, 1); \
                   v += __shfl_xor_sync(0xffffffffu, v, 2); } while (0)

// each 128-thread group loads ITS n-half of the weight image
__device__ __forceinline__ void cpa_half(int slot, int grp, int tg, uint32_t wb_u) {
    const char* gp = reinterpret_cast<const char*>(g_Wpad[slot]) + (size_t)grp * HALF_BYTES;
    uint32_t sb = wb_u + (uint32_t)grp * HALF_BYTES;
    for (int i = tg; i < HALF_CHUNKS; i += 128)
        CPA16(sb + (uint32_t)(i * 16), gp + (size_t)i * 16);
    CPA_COMMIT();
}

// ---------------- merged prep kernel ----------------
__global__ void prep_all(const float* __restrict__ Wgcn, const float* __restrict__ Wvm,
                         const float* __restrict__ Wvd,  const float* __restrict__ W1,
                         const float* __restrict__ Wq_m, const float* __restrict__ Wk_m,
                         const float* __restrict__ Wq_d, const float* __restrict__ Wk_d) {
    int b = blockIdx.x;
    if (b < 64) {
        int slot4 = b >> 4;
        const float* W; int slot;
        switch (slot4) {
            case 0:  W = Wgcn; slot = 0; break;
            case 1:  W = Wvm;  slot = 3; break;
            case 2:  W = Wvd;  slot = 4; break;
            default: W = W1;   slot = 5; break;
        }
        int e0 = (b & 15) * 1024;
        for (int e = e0 + threadIdx.x; e < e0 + 1024; e += blockDim.x) {
            int n = e >> 7, k = e & 127;
            g_Wpad[slot][n * LDW + k] = __float2half_rn(W[k * CDIM + n]);
        }
    } else {
        __shared__ float krow[CDIM];
        int bb = b - 64;
        int which = bb >> 7;
        int n = bb & 127;
        const float* Wq = which ? Wq_d : Wq_m;
        const float* Wk = which ? Wk_d : Wk_m;
        if (threadIdx.x < CDIM) krow[threadIdx.x] = Wk[n * CDIM + threadIdx.x];
        __syncthreads();
        if (threadIdx.x < CDIM) {
            int k = threadIdx.x;
            const float4* q4 = reinterpret_cast<const float4*>(Wq + k * CDIM);
            float s = 0.f;
#pragma unroll
            for (int c4 = 0; c4 < CDIM / 4; ++c4) {
                float4 q = q4[c4];
                s = fmaf(q.x, krow[c4 * 4 + 0], s);
                s = fmaf(q.y, krow[c4 * 4 + 1], s);
                s = fmaf(q.z, krow[c4 * 4 + 2], s);
                s = fmaf(q.w, krow[c4 * 4 + 3], s);
            }
            g_Wpad[which ? 2 : 1][n * LDW + k] = __float2half_rn(s * 0.0883883476483184f);
        }
    }
}

// ---------------- SMEM layout (all tiles fp16) ----------------
#define H_MS   0
#define H_DS   (BT * LDH)
#define H_X1M  (2 * BT * LDH)
#define H_X1D  (3 * BT * LDH)
#define WB_BYTES (4 * BT * LDH * 2)                 // 69632
#define F_R0   ((WB_BYTES + WCOMP_BYTES) / 4)       // 26112 floats
#define F_R1   (F_R0 + 256)
#define F_SAM  (F_R1 + 256)
#define F_SBM  (F_SAM + 64)
#define F_SAD  (F_SBM + 64)
#define F_SBD  (F_SAD + 64)
#define F_SW2  (F_SBD + 64)
#define SMEM_BYTES ((F_SW2 + 128) * 4)              // < 110KB -> 2 CTAs/SM

// ---------------- GEMM (R11 tiling: warp tile m16 x n64) ----------------
__device__ __forceinline__ void gemm_a(uint32_t aX, uint32_t wb, float acc[8][4]) {
#pragma unroll
    for (int ks = 0; ks < 8; ++ks) {
        uint32_t a[4];
        LDSM4(a[0], a[1], a[2], a[3], aX + ks * 32);
#pragma unroll
        for (int np = 0; np < 4; ++np) {
            uint32_t off = (uint32_t)(np * (16 * 2 * LDW) + ks * 32);
            uint32_t b0_, b1_, b2_, b3_;
            LDSM4(b0_, b1_, b2_, b3_, wb + off);
            mma_f16(acc[np * 2],     a, b0_, b1_);
            mma_f16(acc[np * 2 + 1], a, b2_, b3_);
        }
    }
}

__device__ __forceinline__ void gemm_comb(const __half* __restrict__ Xa, const __half* __restrict__ Xb,
                                          float ca0, float cb0, float ca1, float cb1,
                                          uint32_t wb, int r0, int cK, float acc[8][4]) {
    const __half* pa0 = Xa + r0 * LDH;
    const __half* pa1 = Xa + (r0 + 8) * LDH;
    const __half* pb0 = Xb + r0 * LDH;
    const __half* pb1 = Xb + (r0 + 8) * LDH;
#pragma unroll
    for (int ks = 0; ks < 8; ++ks) {
        int c0 = ks * 16 + cK;
        uint32_t a[4];
        {
            float2 v0 = up2(pa0 + c0), u0 = up2(pb0 + c0);
            float2 v1 = up2(pa1 + c0), u1 = up2(pb1 + c0);
            float2 v2 = up2(pa0 + c0 + 8), u2 = up2(pb0 + c0 + 8);
            float2 v3 = up2(pa1 + c0 + 8), u3 = up2(pb1 + c0 + 8);
            a[0] = cvt2h(ca0 * v0.x + cb0 * u0.x, ca0 * v0.y + cb0 * u0.y);
            a[1] = cvt2h(ca1 * v1.x + cb1 * u1.x, ca1 * v1.y + cb1 * u1.y);
            a[2] = cvt2h(ca0 * v2.x + cb0 * u2.x, ca0 * v2.y + cb0 * u2.y);
            a[3] = cvt2h(ca1 * v3.x + cb1 * u3.x, ca1 * v3.y + cb1 * u3.y);
        }
#pragma unroll
        for (int np = 0; np < 4; ++np) {
            uint32_t off = (uint32_t)(np * (16 * 2 * LDW) + ks * 32);
            uint32_t b0_, b1_, b2_, b3_;
            LDSM4(b0_, b1_, b2_, b3_, wb + off);
            mma_f16(acc[np * 2],     a, b0_, b1_);
            mma_f16(acc[np * 2 + 1], a, b2_, b3_);
        }
    }
}

__device__ __forceinline__ void gemm_dual(const __half* __restrict__ Ms, const __half* __restrict__ Ds,
                                          float a0, float b0c, float a1, float b1c,
                                          uint32_t wb, int r0, int cK,
                                          float acc0[8][4], float acc1[8][4]) {
    const __half* pm0 = Ms + r0 * LDH;
    const __half* pm1 = Ms + (r0 + 8) * LDH;
    const __half* pd0 = Ds + r0 * LDH;
    const __half* pd1 = Ds + (r0 + 8) * LDH;
#pragma unroll
    for (int ks = 0; ks < 8; ++ks) {
        int c0 = ks * 16 + cK;
        uint32_t x0[4], x1[4];
        {
            float2 m0 = up2(pm0 + c0), d0 = up2(pd0 + c0);
            float2 m1 = up2(pm1 + c0), d1 = up2(pd1 + c0);
            float2 m2 = up2(pm0 + c0 + 8), d2 = up2(pd0 + c0 + 8);
            float2 m3 = up2(pm1 + c0 + 8), d3 = up2(pd1 + c0 + 8);
            x0[0] = cvt2h(a0 * m0.x + b0c * d0.x, a0 * m0.y + b0c * d0.y);
            x0[1] = cvt2h(a1 * m1.x + b1c * d1.x, a1 * m1.y + b1c * d1.y);
            x0[2] = cvt2h(a0 * m2.x + b0c * d2.x, a0 * m2.y + b0c * d2.y);
            x0[3] = cvt2h(a1 * m3.x + b1c * d3.x, a1 * m3.y + b1c * d3.y);
            x1[0] = cvt2h(b0c * m0.x + a0 * d0.x, b0c * m0.y + a0 * d0.y);
            x1[1] = cvt2h(b1c * m1.x + a1 * d1.x, b1c * m1.y + a1 * d1.y);
            x1[2] = cvt2h(b0c * m2.x + a0 * d2.x, b0c * m2.y + a0 * d2.y);
            x1[3] = cvt2h(b1c * m3.x + a1 * d3.x, b1c * m3.y + a1 * d3.y);
        }
#pragma unroll
        for (int np = 0; np < 4; ++np) {
            uint32_t off = (uint32_t)(np * (16 * 2 * LDW) + ks * 32);
            uint32_t b0_, b1_, b2_, b3_;
            LDSM4(b0_, b1_, b2_, b3_, wb + off);
            mma_f16(acc0[np * 2],     x0, b0_, b1_);
            mma_f16(acc0[np * 2 + 1], x0, b2_, b3_);
            mma_f16(acc1[np * 2],     x1, b0_, b1_);
            mma_f16(acc1[np * 2 + 1], x1, b2_, b3_);
        }
    }
}

__global__ __launch_bounds__(NTHREADS, 2)
void mdi_mma_kernel(const float* __restrict__ em, const float* __restrict__ ed,
                    const float* __restrict__ W2, float* __restrict__ out) {
    extern __shared__ float sh[];
    __half* Ms  = reinterpret_cast<__half*>(sh) + H_MS;
    __half* Ds  = reinterpret_cast<__half*>(sh) + H_DS;
    __half* X1m = reinterpret_cast<__half*>(sh) + H_X1M;
    __half* X1d = reinterpret_cast<__half*>(sh) + H_X1D;
    uint32_t wb_u = smem_u32(reinterpret_cast<char*>(sh) + WB_BYTES);
    float* R0  = sh + F_R0;
    float* R1  = sh + F_R1;
    float* SAm = sh + F_SAM;
    float* SBm = sh + F_SBM;
    float* SAd = sh + F_SAD;
    float* SBd = sh + F_SBD;
    float* SW2 = sh + F_SW2;

    const int tid  = threadIdx.x;
    const int w    = tid >> 5;
    const int lane = tid & 31;
    const int mb    = (w & 3) * 16;       // warp m-tile base row
    const int nbase = (w >> 2) * 64;      // warp n-half base col == group's weight half
    const int r0    = mb + (lane >> 2);
    const int lq    = lane & 3;
    const int cK    = 2 * lq;
    const int nh    = w >> 2;             // n-half / group index
    const int grp   = tid >> 7;           // 128-thread group (== nh)
    const int tg    = tid & 127;
    const int b0 = blockIdx.x * BT;

    // A ldmatrix lane address offset: rows mb+(lane&15), k-half (lane>>4)
    const uint32_t aoff = (uint32_t)((mb + (lane & 15)) * (2 * LDH) + (lane >> 4) * 16);
    const int n_lane = (lane & 7) + ((lane & 16) ? 8 : 0);
    const uint32_t wbl = wb_u + (uint32_t)((nbase + n_lane) * (2 * LDW) + ((lane >> 3) & 1) * 16);

    const uint32_t aX1m = smem_u32(X1m) + aoff;
    const uint32_t aX1d = smem_u32(X1d) + aoff;

    // prefetch Wgcn (each group its half)
    cpa_half(0, grp, tg, wb_u);

    // ---- load inputs -> fp16 tiles, + W2 ----
    {
        const float4* gm = reinterpret_cast<const float4*>(em + (size_t)b0 * CDIM);
        const float4* gd = reinterpret_cast<const float4*>(ed + (size_t)b0 * CDIM);
        for (int i = tid; i < BT * 32; i += NTHREADS) {
            int row = i >> 5, c = i & 31;
            float4 vm = gm[i], vd = gd[i];
            uint2 pm = make_uint2(cvt2h(vm.x, vm.y), cvt2h(vm.z, vm.w));
            uint2 pd = make_uint2(cvt2h(vd.x, vd.y), cvt2h(vd.z, vd.w));
            *reinterpret_cast<uint2*>(Ms + row * LDH + c * 4) = pm;
            *reinterpret_cast<uint2*>(Ds + row * LDH + c * 4) = pd;
        }
        if (tid < CDIM) SW2[tid] = W2[tid];
    }
    __syncthreads();

    // ---- per-batch scalars (quad shfl-reduce) ----
    {
        int rr = tid >> 2, part = tid & 3;
        const __half2* mr = reinterpret_cast<const __half2*>(Ms + rr * LDH + part * 32);
        const __half2* dr = reinterpret_cast<const __half2*>(Ds + rr * LDH + part * 32);
        float dman = 0.f, sm2 = 0.f, sd2 = 0.f, md = 0.f;
#pragma unroll
        for (int k = 0; k < 16; ++k) {
            float2 mv = __half22float2(mr[k]);
            float2 dv = __half22float2(dr[k]);
            dman += fabsf(mv.x - dv.x) + fabsf(mv.y - dv.y);
            sm2 += mv.x * mv.x + mv.y * mv.y;
            sd2 += dv.x * dv.x + dv.y * dv.y;
            md  += mv.x * dv.x + mv.y * dv.y;
        }
        QR(dman); QR(sm2); QR(sd2); QR(md);
        if (part == 0) {
            float s3 = 1.f / (1.f + dman);
            float c = md / (sqrtf(sm2 + EPSF) * sqrtf(sd2 + EPSF));
            if (c < 0.f) c *= 0.01f;
            float s1 = 1.f / (1.f + c);
            SAm[rr] = fminf(s3, s1);
            SBm[rr] = fminf(dman * s3, c * s1);
        }
    }
    CPA_WAIT(0);
    __syncthreads();      // full: Wgcn halves + scalars visible to all

    // ===== pass 0 (merged GCN): x1m/x1d = relu(u @ Wgcn) + x0 =====
    {
        float acc0[8][4] = {}, acc1[8][4] = {};
        gemm_dual(Ms, Ds, SAm[r0], SBm[r0], SAm[r0 + 8], SBm[r0 + 8],
                  wbl, r0, cK, acc0, acc1);
        GBAR(grp);                       // my group done reading its Wgcn half
        cpa_half(1, grp, tg, wb_u);      // gM0 half (issued before epilogue)
#pragma unroll
        for (int nt = 0; nt < 8; ++nt) {
            int col = nbase + nt * 8 + cK;
            float2 m0 = up2(&Ms[r0 * LDH + col]);
            float2 m1 = up2(&Ms[(r0 + 8) * LDH + col]);
            float2 d0 = up2(&Ds[r0 * LDH + col]);
            float2 d1 = up2(&Ds[(r0 + 8) * LDH + col]);
            *reinterpret_cast<uint32_t*>(&X1m[r0 * LDH + col]) =
                cvt2h(fmaxf(acc0[nt][0], 0.f) + m0.x, fmaxf(acc0[nt][1], 0.f) + m0.y);
            *reinterpret_cast<uint32_t*>(&X1m[(r0 + 8) * LDH + col]) =
                cvt2h(fmaxf(acc0[nt][2], 0.f) + m1.x, fmaxf(acc0[nt][3], 0.f) + m1.y);
            *reinterpret_cast<uint32_t*>(&X1d[r0 * LDH + col]) =
                cvt2h(fmaxf(acc1[nt][0], 0.f) + d0.x, fmaxf(acc1[nt][1], 0.f) + d0.y);
            *reinterpret_cast<uint32_t*>(&X1d[(r0 + 8) * LDH + col]) =
                cvt2h(fmaxf(acc1[nt][2], 0.f) + d1.x, fmaxf(acc1[nt][3], 0.f) + d1.y);
        }
    }
    __syncthreads();                     // X1 tiles visible to all

    // ===== passes 1/2: attention scores per branch =====
#pragma unroll 1
    for (int br = 0; br < 2; ++br) {
        const __half* X1 = br ? X1d : X1m;
        const __half* X0 = br ? Ds : Ms;
        uint32_t aX1 = br ? aX1d : aX1m;
        float acc[8][4] = {};
        CPA_WAIT(0); GBAR(grp);          // my gM half ready & group-visible
        gemm_a(aX1, wbl, acc);
        GBAR(grp);                       // group done reading its half
        cpa_half(br ? 3 : 2, grp, tg, wb_u);   // gM1 then Wv_m
        {
            float q00 = 0.f, q10 = 0.f, q01 = 0.f, q11 = 0.f;
#pragma unroll
            for (int nt = 0; nt < 8; ++nt) {
                int col = nbase + nt * 8 + cK;
                float2 a0 = up2(&X0[r0 * LDH + col]);
                float2 a1 = up2(&X1[r0 * LDH + col]);
                float2 c0 = up2(&X0[(r0 + 8) * LDH + col]);
                float2 c1 = up2(&X1[(r0 + 8) * LDH + col]);
                q00 += acc[nt][0] * a0.x + acc[nt][1] * a0.y;
                q10 += acc[nt][0] * a1.x + acc[nt][1] * a1.y;
                q01 += acc[nt][2] * c0.x + acc[nt][3] * c0.y;
                q11 += acc[nt][2] * c1.x + acc[nt][3] * c1.y;
            }
            QR(q00); QR(q10); QR(q01); QR(q11);
            if (lq == 0) {
                R0[r0 * 2 + nh] = q00;
                R1[r0 * 2 + nh] = q10;
                R0[(r0 + 8) * 2 + nh] = q01;
                R1[(r0 + 8) * 2 + nh] = q11;
            }
        }
        __syncthreads();                 // partials visible (R0/R1 reuse + softmax)
        if (tid < BT) {
            float s0  = R0[tid * 2] + R0[tid * 2 + 1];
            float s1v = R1[tid * 2] + R1[tid * 2 + 1];
            float mx = fmaxf(s0, s1v);
            float e0 = __expf(s0 - mx), e1 = __expf(s1v - mx);
            float inv = 1.f / (e0 + e1);
            if (br == 0) { SAm[tid] = e0 * inv; SBm[tid] = e1 * inv; }
            else         { SAd[tid] = e0 * inv; SBd[tid] = e1 * inv; }
        }
        if (br == 0) __syncthreads();    // SAm/SBm + R0/R1 free for branch d
    }

    // ===== pass 3: mLA = (a0m*x0m + a1m*x1m) @ Wv_m, kept in registers =====
    // (SAm/SBm synced after br0; X1m unchanged since pass0 sync; no full sync needed
    //  after br1 softmax here — pass 3 doesn't read SAd/SBd or R0/R1.)
    float mla[8][4] = {};
    CPA_WAIT(0); GBAR(grp);              // my Wv_m half ready
    gemm_comb(Ms, X1m, SAm[r0], SBm[r0], SAm[r0 + 8], SBm[r0 + 8], wbl, r0, cK, mla);
    GBAR(grp);
    cpa_half(4, grp, tg, wb_u);          // Wv_d half
    __syncthreads();                     // SAd/SBd (br1 softmax) visible; X1m reads done

    // ===== pass 4: ne = ((a0d*x0d + a1d*x1d) @ Wv_d) * mLA -> X1m =====
    {
        float acc[8][4] = {};
        CPA_WAIT(0); GBAR(grp);          // my Wv_d half ready
        gemm_comb(Ds, X1d, SAd[r0], SBd[r0], SAd[r0 + 8], SBd[r0 + 8], wbl, r0, cK, acc);
        GBAR(grp);
        cpa_half(5, grp, tg, wb_u);      // W1 half
#pragma unroll
        for (int nt = 0; nt < 8; ++nt) {
            int col = nbase + nt * 8 + cK;
            *reinterpret_cast<uint32_t*>(&X1m[r0 * LDH + col]) =
                cvt2h(acc[nt][0] * mla[nt][0], acc[nt][1] * mla[nt][1]);
            *reinterpret_cast<uint32_t*>(&X1m[(r0 + 8) * LDH + col]) =
                cvt2h(acc[nt][2] * mla[nt][2], acc[nt][3] * mla[nt][3]);
        }
    }
    __syncthreads();                     // ne (X1m) visible to all

    // ===== pass 5: pre = relu(ne @ W1) . W2 ; out = sigmoid =====
    {
        float acc[8][4] = {};
        CPA_WAIT(0); GBAR(grp);          // my W1 half ready
        gemm_a(aX1m, wbl, acc);
        float p0 = 0.f, p1 = 0.f;
#pragma unroll
        for (int nt = 0; nt < 8; ++nt) {
            int col = nbase + nt * 8 + cK;
            p0 += fmaxf(acc[nt][0], 0.f) * SW2[col] + fmaxf(acc[nt][1], 0.f) * SW2[col + 1];
            p1 += fmaxf(acc[nt][2], 0.f) * SW2[col] + fmaxf(acc[nt][3], 0.f) * SW2[col + 1];
        }
        QR(p0); QR(p1);
        if (lq == 0) {
            R0[r0 * 2 + nh] = p0;
            R0[(r0 + 8) * 2 + nh] = p1;
        }
    }
    __syncthreads();
    if (tid < BT) {
        float pre = R0[tid * 2] + R0[tid * 2 + 1];
        out[b0 + tid] = 1.f / (1.f + __expf(-pre));
    }
}

extern "C" void kernel_launch(void* const* d_in, const int* in_sizes, int n_in,
                              void* d_out, int out_size) {
    const float* em    = (const float*)d_in[0];
    const float* ed    = (const float*)d_in[1];
    const float* Wgcn  = (const float*)d_in[2];
    const float* Wq_m  = (const float*)d_in[3];
    const float* Wk_m  = (const float*)d_in[4];
    const float* Wv_m  = (const float*)d_in[5];
    const float* Wq_d  = (const float*)d_in[6];
    const float* Wk_d  = (const float*)d_in[7];
    const float* Wv_d  = (const float*)d_in[8];
    const float* W1    = (const float*)d_in[9];
    const float* W2    = (const float*)d_in[10];
    float* out = (float*)d_out;

    cudaFuncSetAttribute(mdi_mma_kernel, cudaFuncAttributeMaxDynamicSharedMemorySize, SMEM_BYTES);

    int B = out_size;   // 262144
    prep_all<<<320, 256>>>(Wgcn, Wv_m, Wv_d, W1, Wq_m, Wk_m, Wq_d, Wk_d);
    mdi_mma_kernel<<<B / BT, NTHREADS, SMEM_BYTES>>>(em, ed, W2, out);
}